// round 2
// baseline (speedup 1.0000x reference)
#include <cuda_runtime.h>
#include <math.h>

#define NB 131072
#define ND 512
#define NS 64
#define NH 128
#define NCHUNK 128
#define CHUNK_ROWS (NB / NCHUNK)   /* 1024 */

// ---- scratch (static device globals; no runtime allocation) ----
static __device__ float g_h[(size_t)NB * NH];            // 67 MB  relu hidden
static __device__ float g_w[(size_t)NB * NS];            // 33 MB  softmax weights
static __device__ float g_upd[(size_t)NB * ND];          // 268 MB tanh updates
static __device__ float g_part[(size_t)NCHUNK * NS * ND];// 16 MB  split-K partials

// ============================================================
// K1: h = relu(X @ W1 + b1)   [B,512] x [512,128] -> [B,128]
// block tile 128x128, thread 8x8, BK=16
// ============================================================
__global__ __launch_bounds__(256) void k1_gemm_relu(
    const float* __restrict__ X, const float* __restrict__ W1,
    const float* __restrict__ b1) {
  __shared__ __align__(16) float As[16][128];
  __shared__ __align__(16) float Bs[16][128];
  const int tid  = threadIdx.x;
  const int row0 = blockIdx.x * 128;
  const int tx = tid & 15, ty = tid >> 4;
  float acc[8][8];
#pragma unroll
  for (int i = 0; i < 8; i++)
#pragma unroll
    for (int j = 0; j < 8; j++) acc[i][j] = 0.f;

  for (int k0 = 0; k0 < 512; k0 += 16) {
#pragma unroll
    for (int l = 0; l < 2; l++) {            // A tile: 128 rows x 16 k
      int idx = tid + l * 256;
      int r = idx >> 2, q = idx & 3;
      float4 v = *(const float4*)(X + (size_t)(row0 + r) * 512 + k0 + q * 4);
      As[q*4+0][r] = v.x; As[q*4+1][r] = v.y;
      As[q*4+2][r] = v.z; As[q*4+3][r] = v.w;
    }
#pragma unroll
    for (int l = 0; l < 2; l++) {            // B tile: 16 k x 128 n
      int idx = tid + l * 256;
      int k = idx >> 5, n4 = idx & 31;
      float4 v = *(const float4*)(W1 + (size_t)(k0 + k) * 128 + n4 * 4);
      *(float4*)(&Bs[k][n4 * 4]) = v;
    }
    __syncthreads();
#pragma unroll
    for (int kk = 0; kk < 16; kk++) {
      float a[8], b[8];
#pragma unroll
      for (int i = 0; i < 8; i++) a[i] = As[kk][ty*8 + i];
#pragma unroll
      for (int j = 0; j < 8; j++) b[j] = Bs[kk][tx*8 + j];
#pragma unroll
      for (int i = 0; i < 8; i++)
#pragma unroll
        for (int j = 0; j < 8; j++) acc[i][j] = fmaf(a[i], b[j], acc[i][j]);
    }
    __syncthreads();
  }
#pragma unroll
  for (int i = 0; i < 8; i++) {
    int row = row0 + ty*8 + i;
#pragma unroll
    for (int j = 0; j < 8; j++) {
      int col = tx*8 + j;
      float c = acc[i][j] + b1[col];
      g_h[(size_t)row * 128 + col] = c > 0.f ? c : 0.f;
    }
  }
}

// ============================================================
// K2: logits = h @ W2 + b2 ; w = softmax(logits)   per row (S=64)
// 256 threads = 8 warps; each warp does 8 rows; W2 (128x64) in smem
// ============================================================
__global__ __launch_bounds__(256) void k2_softmax(
    const float* __restrict__ W2, const float* __restrict__ b2) {
  __shared__ __align__(16) float w2s[128 * 64];
  __shared__ __align__(16) float hs[8][128];
  __shared__ float b2s[64];
  const int tid = threadIdx.x;
  for (int i = tid; i < (128 * 64) / 4; i += 256)
    ((float4*)w2s)[i] = ((const float4*)W2)[i];
  if (tid < 64) b2s[tid] = b2[tid];
  __syncthreads();

  const int warp = tid >> 5, lane = tid & 31;
  const int row_base = blockIdx.x * 64 + warp * 8;
  for (int r = 0; r < 8; r++) {
    int row = row_base + r;
    ((float4*)hs[warp])[lane] = ((const float4*)(g_h + (size_t)row * 128))[lane];
    __syncwarp();
    float a0 = b2s[lane], a1 = b2s[lane + 32];
#pragma unroll 8
    for (int k = 0; k < 128; k++) {
      float hk = hs[warp][k];
      a0 = fmaf(hk, w2s[k * 64 + lane], a0);
      a1 = fmaf(hk, w2s[k * 64 + lane + 32], a1);
    }
    float m = fmaxf(a0, a1);
#pragma unroll
    for (int o = 16; o > 0; o >>= 1) m = fmaxf(m, __shfl_xor_sync(~0u, m, o));
    float e0 = __expf(a0 - m), e1 = __expf(a1 - m);
    float s = e0 + e1;
#pragma unroll
    for (int o = 16; o > 0; o >>= 1) s += __shfl_xor_sync(~0u, s, o);
    float inv = 1.f / s;
    g_w[(size_t)row * 64 + lane]      = e0 * inv;
    g_w[(size_t)row * 64 + lane + 32] = e1 * inv;
    __syncwarp();
  }
}

// ============================================================
// K3: selected = w @ ref   [B,64] x [64,512] -> [B,512] (to d_out)
// ============================================================
__global__ __launch_bounds__(256) void k3_select(
    const float* __restrict__ REF, float* __restrict__ OUT_SEL) {
  __shared__ __align__(16) float As[16][128];
  __shared__ __align__(16) float Bs[16][128];
  const int tid  = threadIdx.x;
  const int row0 = blockIdx.x * 128;
  const int col0 = blockIdx.y * 128;
  const int tx = tid & 15, ty = tid >> 4;
  float acc[8][8];
#pragma unroll
  for (int i = 0; i < 8; i++)
#pragma unroll
    for (int j = 0; j < 8; j++) acc[i][j] = 0.f;

  for (int k0 = 0; k0 < 64; k0 += 16) {
#pragma unroll
    for (int l = 0; l < 2; l++) {
      int idx = tid + l * 256;
      int r = idx >> 2, q = idx & 3;
      float4 v = *(const float4*)(g_w + (size_t)(row0 + r) * 64 + k0 + q * 4);
      As[q*4+0][r] = v.x; As[q*4+1][r] = v.y;
      As[q*4+2][r] = v.z; As[q*4+3][r] = v.w;
    }
#pragma unroll
    for (int l = 0; l < 2; l++) {
      int idx = tid + l * 256;
      int k = idx >> 5, n4 = idx & 31;
      float4 v = *(const float4*)(REF + (size_t)(k0 + k) * 512 + col0 + n4 * 4);
      *(float4*)(&Bs[k][n4 * 4]) = v;
    }
    __syncthreads();
#pragma unroll
    for (int kk = 0; kk < 16; kk++) {
      float a[8], b[8];
#pragma unroll
      for (int i = 0; i < 8; i++) a[i] = As[kk][ty*8 + i];
#pragma unroll
      for (int j = 0; j < 8; j++) b[j] = Bs[kk][tx*8 + j];
#pragma unroll
      for (int i = 0; i < 8; i++)
#pragma unroll
        for (int j = 0; j < 8; j++) acc[i][j] = fmaf(a[i], b[j], acc[i][j]);
    }
    __syncthreads();
  }
#pragma unroll
  for (int i = 0; i < 8; i++) {
    int row = row0 + ty*8 + i;
#pragma unroll
    for (int j = 0; j < 8; j++)
      OUT_SEL[(size_t)row * 512 + col0 + tx*8 + j] = acc[i][j];
  }
}

// ============================================================
// K4: updates = tanh([X | selected] @ Wu + bu)  [B,1024]x[1024,512]
// ============================================================
__global__ __launch_bounds__(256) void k4_gemm_tanh(
    const float* __restrict__ X, const float* __restrict__ SEL,
    const float* __restrict__ WU, const float* __restrict__ bu) {
  __shared__ __align__(16) float As[16][128];
  __shared__ __align__(16) float Bs[16][128];
  const int tid  = threadIdx.x;
  const int row0 = blockIdx.x * 128;
  const int col0 = blockIdx.y * 128;
  const int tx = tid & 15, ty = tid >> 4;
  float acc[8][8];
#pragma unroll
  for (int i = 0; i < 8; i++)
#pragma unroll
    for (int j = 0; j < 8; j++) acc[i][j] = 0.f;

  for (int k0 = 0; k0 < 1024; k0 += 16) {
    const float* Asrc = (k0 < 512) ? X : SEL;
    const int kb = (k0 < 512) ? k0 : (k0 - 512);
#pragma unroll
    for (int l = 0; l < 2; l++) {
      int idx = tid + l * 256;
      int r = idx >> 2, q = idx & 3;
      float4 v = *(const float4*)(Asrc + (size_t)(row0 + r) * 512 + kb + q * 4);
      As[q*4+0][r] = v.x; As[q*4+1][r] = v.y;
      As[q*4+2][r] = v.z; As[q*4+3][r] = v.w;
    }
#pragma unroll
    for (int l = 0; l < 2; l++) {
      int idx = tid + l * 256;
      int k = idx >> 5, n4 = idx & 31;
      float4 v = *(const float4*)(WU + (size_t)(k0 + k) * 512 + col0 + n4 * 4);
      *(float4*)(&Bs[k][n4 * 4]) = v;
    }
    __syncthreads();
#pragma unroll
    for (int kk = 0; kk < 16; kk++) {
      float a[8], b[8];
#pragma unroll
      for (int i = 0; i < 8; i++) a[i] = As[kk][ty*8 + i];
#pragma unroll
      for (int j = 0; j < 8; j++) b[j] = Bs[kk][tx*8 + j];
#pragma unroll
      for (int i = 0; i < 8; i++)
#pragma unroll
        for (int j = 0; j < 8; j++) acc[i][j] = fmaf(a[i], b[j], acc[i][j]);
    }
    __syncthreads();
  }
#pragma unroll
  for (int i = 0; i < 8; i++) {
    int row = row0 + ty*8 + i;
#pragma unroll
    for (int j = 0; j < 8; j++) {
      int col = col0 + tx*8 + j;
      g_upd[(size_t)row * 512 + col] = tanhf(acc[i][j] + bu[col]);
    }
  }
}

// ============================================================
// K5a: split-K partials of w^T @ updates
// grid = NCHUNK*4; block computes C-tile [64 s x 128 d] over 1024 rows
// thread: 8 s x 4 d cells  (ts = tid/32 -> broadcast ws reads)
// ============================================================
__global__ __launch_bounds__(256) void k5a_partials() {
  const int dq    = blockIdx.x & 3;
  const int chunk = blockIdx.x >> 2;
  const int d0 = dq * 128;
  const int b0 = chunk * CHUNK_ROWS;
  __shared__ __align__(16) float ws[8][64];
  __shared__ __align__(16) float us[8][128];
  const int tid = threadIdx.x;
  const int ts = tid >> 5;       // 0..7  (all lanes of a warp share ts)
  const int td = tid & 31;       // 0..31
  float acc[8][4];
#pragma unroll
  for (int i = 0; i < 8; i++)
#pragma unroll
    for (int j = 0; j < 4; j++) acc[i][j] = 0.f;

  for (int k0 = 0; k0 < CHUNK_ROWS; k0 += 8) {
    if (tid < 128) {             // w tile: 8 rows x 64
      int r = tid >> 4, c4 = tid & 15;
      float4 v = *(const float4*)(g_w + (size_t)(b0 + k0 + r) * 64 + c4 * 4);
      *(float4*)(&ws[r][c4 * 4]) = v;
    }
    {                            // upd tile: 8 rows x 128
      int r = tid >> 5, c4 = tid & 31;
      float4 v = *(const float4*)(g_upd + (size_t)(b0 + k0 + r) * 512 + d0 + c4 * 4);
      *(float4*)(&us[r][c4 * 4]) = v;
    }
    __syncthreads();
#pragma unroll
    for (int kk = 0; kk < 8; kk++) {
      float4 u = *(const float4*)(&us[kk][td * 4]);
      float wv[8];
#pragma unroll
      for (int i = 0; i < 8; i++) wv[i] = ws[kk][ts*8 + i];
#pragma unroll
      for (int i = 0; i < 8; i++) {
        acc[i][0] = fmaf(wv[i], u.x, acc[i][0]);
        acc[i][1] = fmaf(wv[i], u.y, acc[i][1]);
        acc[i][2] = fmaf(wv[i], u.z, acc[i][2]);
        acc[i][3] = fmaf(wv[i], u.w, acc[i][3]);
      }
    }
    __syncthreads();
  }
  float* p = g_part + (size_t)chunk * (NS * ND);
#pragma unroll
  for (int i = 0; i < 8; i++) {
    float4 v = make_float4(acc[i][0], acc[i][1], acc[i][2], acc[i][3]);
    *(float4*)(p + (size_t)(ts*8 + i) * 512 + d0 + td * 4) = v;
  }
}

// ============================================================
// K5b: new_ref = ref + 0.01 * sum(partials)   (deterministic order)
// ============================================================
__global__ __launch_bounds__(256) void k5b_reduce(
    const float* __restrict__ REF, float* __restrict__ OUT_REF) {
  const int idx = blockIdx.x * 256 + threadIdx.x;   // 0..32767
  float s = 0.f;
#pragma unroll 8
  for (int c = 0; c < NCHUNK; c++) s += g_part[(size_t)c * (NS * ND) + idx];
  OUT_REF[idx] = REF[idx] + 0.01f * s;
}

// ============================================================
extern "C" void kernel_launch(void* const* d_in, const int* in_sizes, int n_in,
                              void* d_out, int out_size) {
  const float* X   = (const float*)d_in[0];  // [B, D]
  const float* REF = (const float*)d_in[1];  // [S, D]
  const float* W1  = (const float*)d_in[2];  // [D, H]
  const float* b1  = (const float*)d_in[3];  // [H]
  const float* W2  = (const float*)d_in[4];  // [H, S]
  const float* b2  = (const float*)d_in[5];  // [S]
  const float* WU  = (const float*)d_in[6];  // [2D, D]
  const float* bu  = (const float*)d_in[7];  // [D]

  float* out_sel = (float*)d_out;                       // [B, D]
  float* out_ref = (float*)d_out + (size_t)NB * ND;     // [S, D]

  k1_gemm_relu<<<NB / 128, 256>>>(X, W1, b1);
  k2_softmax<<<NB / 64, 256>>>(W2, b2);
  k3_select<<<dim3(NB / 128, 4), 256>>>(REF, out_sel);
  k4_gemm_tanh<<<dim3(NB / 128, 4), 256>>>(X, out_sel, WU, bu);
  k5a_partials<<<NCHUNK * 4, 256>>>();
  k5b_reduce<<<(NS * ND) / 256, 256>>>(REF, out_ref);
}

// round 5
// speedup vs baseline: 2.6907x; 2.6907x over previous
#include <cuda_runtime.h>
#include <math.h>
#include <stdint.h>

#define NB 131072
#define ND 512
#define NS 64
#define NH 128
#define NCHUNK 128
#define CHUNK_ROWS (NB / NCHUNK)   /* 1024 */

// ---- scratch (static device globals; no runtime allocation) ----
static __device__ float g_h[(size_t)NB * NH];             // relu hidden
static __device__ float g_w[(size_t)NB * NS];             // softmax weights
static __device__ float g_upd[(size_t)NB * ND];           // tanh updates
static __device__ float g_part[(size_t)NCHUNK * NS * ND]; // split-K partials
static __device__ float g_w1T[(size_t)NH * ND];           // [128][512]
static __device__ float g_wuT[(size_t)ND * 2 * ND];       // [512][1024]
static __device__ float g_refT[(size_t)ND * NS];          // [512][64]

// ============================================================
// helpers
// ============================================================
__device__ __forceinline__ float f2tf32f(float x) {
  uint32_t r;
  asm("cvt.rna.tf32.f32 %0, %1;" : "=r"(r) : "f"(x));
  return __uint_as_float(r);
}
__device__ __forceinline__ void mma_tf32(float c[4], const uint32_t a[4],
                                         const uint32_t b[2]) {
  asm volatile(
      "mma.sync.aligned.m16n8k8.row.col.f32.tf32.tf32.f32 "
      "{%0,%1,%2,%3}, {%4,%5,%6,%7}, {%8,%9}, {%0,%1,%2,%3};"
      : "+f"(c[0]), "+f"(c[1]), "+f"(c[2]), "+f"(c[3])
      : "r"(a[0]), "r"(a[1]), "r"(a[2]), "r"(a[3]), "r"(b[0]), "r"(b[1]));
}
template <int ACT> __device__ __forceinline__ float actf(float x) {
  if (ACT == 1) return x > 0.f ? x : 0.f;
  if (ACT == 2) return tanhf(x);
  return x;
}

// ============================================================
// generic 32x32 transpose: dst[C][R] = src[R][C]^T
// ============================================================
__global__ void k_transpose(const float* __restrict__ src, float* __restrict__ dst,
                            int R, int C) {
  __shared__ float t[32][33];
  int c0 = blockIdx.x * 32, r0 = blockIdx.y * 32;
  int x = threadIdx.x, y = threadIdx.y;
#pragma unroll
  for (int i = 0; i < 32; i += 8)
    t[y + i][x] = src[(size_t)(r0 + y + i) * C + c0 + x];
  __syncthreads();
#pragma unroll
  for (int i = 0; i < 32; i += 8)
    dst[(size_t)(c0 + y + i) * R + r0 + x] = t[x][y + i];
}

// ============================================================
// tf32 mma.sync GEMM: OUT[m, n] = ACT( sum_k A[m,k]*BT[n,k] + bias[n] )
// CTA tile 128x128, BK=32; 8 warps in 4(m) x 2(n); warp tile 32x64
// (2 x 8 m16n8k8 tiles). A optionally split at k=512 (concat input).
// ============================================================
template <int ACT, int KTOT, bool ASPLIT>
__global__ __launch_bounds__(256, 2) void gemm_mma(
    const float* __restrict__ A0, const float* __restrict__ A1, int a_stride,
    const float* __restrict__ BT, const float* __restrict__ bias,
    float* __restrict__ OUT, int o_stride) {
  __shared__ float As[128][36];
  __shared__ float Bs[128][36];
  const int tid = threadIdx.x, wid = tid >> 5, lane = tid & 31;
  const int n0 = blockIdx.x * 128;
  const int m0 = blockIdx.y * 128;
  const int wm = (wid & 3) * 32;     // warp m offset in CTA tile
  const int wn = (wid >> 2) * 64;    // warp n offset in CTA tile
  const int g = lane >> 2, t = lane & 3;

  float acc[2][8][4];
#pragma unroll
  for (int mt = 0; mt < 2; mt++)
#pragma unroll
    for (int nt = 0; nt < 8; nt++)
#pragma unroll
      for (int r = 0; r < 4; r++) acc[mt][nt][r] = 0.f;

  constexpr int NCH = KTOT / 32;
#pragma unroll 1
  for (int c = 0; c < NCH; c++) {
    const int k0 = c * 32;
    const float* Asrc = (!ASPLIT || k0 < 512) ? A0 : A1;
    const int ko = (!ASPLIT || k0 < 512) ? k0 : k0 - 512;
    // A tile: 128 rows x 32 k (convert to tf32 on the way in)
#pragma unroll
    for (int l = 0; l < 4; l++) {
      int lin = tid + l * 256;
      int row = lin >> 3, c4 = lin & 7;
      float4 v = *(const float4*)(Asrc + (size_t)(m0 + row) * a_stride + ko + c4 * 4);
      As[row][c4 * 4 + 0] = f2tf32f(v.x);
      As[row][c4 * 4 + 1] = f2tf32f(v.y);
      As[row][c4 * 4 + 2] = f2tf32f(v.z);
      As[row][c4 * 4 + 3] = f2tf32f(v.w);
    }
    // B tile: 128 n-rows x 32 k
#pragma unroll
    for (int l = 0; l < 4; l++) {
      int lin = tid + l * 256;
      int row = lin >> 3, c4 = lin & 7;
      float4 v = *(const float4*)(BT + (size_t)(n0 + row) * KTOT + k0 + c4 * 4);
      Bs[row][c4 * 4 + 0] = f2tf32f(v.x);
      Bs[row][c4 * 4 + 1] = f2tf32f(v.y);
      Bs[row][c4 * 4 + 2] = f2tf32f(v.z);
      Bs[row][c4 * 4 + 3] = f2tf32f(v.w);
    }
    __syncthreads();
#pragma unroll
    for (int ks = 0; ks < 4; ks++) {
      const int kk = ks * 8;
      uint32_t a[2][4], b[8][2];
#pragma unroll
      for (int mt = 0; mt < 2; mt++) {
        const int rb = wm + mt * 16;
        a[mt][0] = __float_as_uint(As[rb + g][kk + t]);
        a[mt][1] = __float_as_uint(As[rb + 8 + g][kk + t]);
        a[mt][2] = __float_as_uint(As[rb + g][kk + t + 4]);
        a[mt][3] = __float_as_uint(As[rb + 8 + g][kk + t + 4]);
      }
#pragma unroll
      for (int nt = 0; nt < 8; nt++) {
        const int nb = wn + nt * 8;
        b[nt][0] = __float_as_uint(Bs[nb + g][kk + t]);
        b[nt][1] = __float_as_uint(Bs[nb + g][kk + t + 4]);
      }
#pragma unroll
      for (int mt = 0; mt < 2; mt++)
#pragma unroll
        for (int nt = 0; nt < 8; nt++) mma_tf32(acc[mt][nt], a[mt], b[nt]);
    }
    __syncthreads();
  }

  // epilogue: each lane owns rows {g, g+8}, cols {t*2, t*2+1} per tile
#pragma unroll
  for (int mt = 0; mt < 2; mt++) {
#pragma unroll
    for (int nt = 0; nt < 8; nt++) {
      const int row = m0 + wm + mt * 16 + g;
      const int col = n0 + wn + nt * 8 + t * 2;
      float b0 = 0.f, b1 = 0.f;
      if (bias) { b0 = bias[col]; b1 = bias[col + 1]; }
      float2 v0 = make_float2(actf<ACT>(acc[mt][nt][0] + b0),
                              actf<ACT>(acc[mt][nt][1] + b1));
      float2 v1 = make_float2(actf<ACT>(acc[mt][nt][2] + b0),
                              actf<ACT>(acc[mt][nt][3] + b1));
      *(float2*)(OUT + (size_t)row * o_stride + col) = v0;
      *(float2*)(OUT + (size_t)(row + 8) * o_stride + col) = v1;
    }
  }
}

// ============================================================
// K2: logits = h @ W2 + b2 ; w = softmax(logits)   per row (S=64)
// ============================================================
__global__ __launch_bounds__(256) void k2_softmax(
    const float* __restrict__ W2, const float* __restrict__ b2) {
  __shared__ __align__(16) float w2s[128 * 64];
  __shared__ __align__(16) float hs[8][128];
  __shared__ float b2s[64];
  const int tid = threadIdx.x;
  for (int i = tid; i < (128 * 64) / 4; i += 256)
    ((float4*)w2s)[i] = ((const float4*)W2)[i];
  if (tid < 64) b2s[tid] = b2[tid];
  __syncthreads();

  const int warp = tid >> 5, lane = tid & 31;
  const int row_base = blockIdx.x * 64 + warp * 8;
  for (int r = 0; r < 8; r++) {
    int row = row_base + r;
    ((float4*)hs[warp])[lane] = ((const float4*)(g_h + (size_t)row * 128))[lane];
    __syncwarp();
    float a0 = b2s[lane], a1 = b2s[lane + 32];
#pragma unroll 8
    for (int k = 0; k < 128; k++) {
      float hk = hs[warp][k];
      a0 = fmaf(hk, w2s[k * 64 + lane], a0);
      a1 = fmaf(hk, w2s[k * 64 + lane + 32], a1);
    }
    float m = fmaxf(a0, a1);
#pragma unroll
    for (int o = 16; o > 0; o >>= 1) m = fmaxf(m, __shfl_xor_sync(~0u, m, o));
    float e0 = __expf(a0 - m), e1 = __expf(a1 - m);
    float s = e0 + e1;
#pragma unroll
    for (int o = 16; o > 0; o >>= 1) s += __shfl_xor_sync(~0u, s, o);
    float inv = 1.f / s;
    g_w[(size_t)row * 64 + lane]      = e0 * inv;
    g_w[(size_t)row * 64 + lane + 32] = e1 * inv;
    __syncwarp();
  }
}

// ============================================================
// K5a: split-K partials of w^T @ updates   (FFMA; convert next round)
// ============================================================
__global__ __launch_bounds__(256) void k5a_partials() {
  const int dq    = blockIdx.x & 3;
  const int chunk = blockIdx.x >> 2;
  const int d0 = dq * 128;
  const int b0 = chunk * CHUNK_ROWS;
  __shared__ __align__(16) float ws[8][64];
  __shared__ __align__(16) float us[8][128];
  const int tid = threadIdx.x;
  const int ts = tid >> 5;
  const int td = tid & 31;
  float acc[8][4];
#pragma unroll
  for (int i = 0; i < 8; i++)
#pragma unroll
    for (int j = 0; j < 4; j++) acc[i][j] = 0.f;

  for (int k0 = 0; k0 < CHUNK_ROWS; k0 += 8) {
    if (tid < 128) {
      int r = tid >> 4, c4 = tid & 15;
      float4 v = *(const float4*)(g_w + (size_t)(b0 + k0 + r) * 64 + c4 * 4);
      *(float4*)(&ws[r][c4 * 4]) = v;
    }
    {
      int r = tid >> 5, c4 = tid & 31;
      float4 v = *(const float4*)(g_upd + (size_t)(b0 + k0 + r) * 512 + d0 + c4 * 4);
      *(float4*)(&us[r][c4 * 4]) = v;
    }
    __syncthreads();
#pragma unroll
    for (int kk = 0; kk < 8; kk++) {
      float4 u = *(const float4*)(&us[kk][td * 4]);
      float wv[8];
#pragma unroll
      for (int i = 0; i < 8; i++) wv[i] = ws[kk][ts * 8 + i];
#pragma unroll
      for (int i = 0; i < 8; i++) {
        acc[i][0] = fmaf(wv[i], u.x, acc[i][0]);
        acc[i][1] = fmaf(wv[i], u.y, acc[i][1]);
        acc[i][2] = fmaf(wv[i], u.z, acc[i][2]);
        acc[i][3] = fmaf(wv[i], u.w, acc[i][3]);
      }
    }
    __syncthreads();
  }
  float* p = g_part + (size_t)chunk * (NS * ND);
#pragma unroll
  for (int i = 0; i < 8; i++) {
    float4 v = make_float4(acc[i][0], acc[i][1], acc[i][2], acc[i][3]);
    *(float4*)(p + (size_t)(ts * 8 + i) * 512 + d0 + td * 4) = v;
  }
}

// ============================================================
// K5b: new_ref = ref + 0.01 * sum(partials)   (deterministic order)
// ============================================================
__global__ __launch_bounds__(256) void k5b_reduce(
    const float* __restrict__ REF, float* __restrict__ OUT_REF) {
  const int idx = blockIdx.x * 256 + threadIdx.x;
  float s = 0.f;
#pragma unroll 8
  for (int c = 0; c < NCHUNK; c++) s += g_part[(size_t)c * (NS * ND) + idx];
  OUT_REF[idx] = REF[idx] + 0.01f * s;
}

// ============================================================
extern "C" void kernel_launch(void* const* d_in, const int* in_sizes, int n_in,
                              void* d_out, int out_size) {
  const float* X   = (const float*)d_in[0];
  const float* REF = (const float*)d_in[1];
  const float* W1  = (const float*)d_in[2];
  const float* b1  = (const float*)d_in[3];
  const float* W2  = (const float*)d_in[4];
  const float* b2  = (const float*)d_in[5];
  const float* WU  = (const float*)d_in[6];
  const float* bu  = (const float*)d_in[7];

  float* out_sel = (float*)d_out;
  float* out_ref = (float*)d_out + (size_t)NB * ND;

  float *w1T, *wuT, *refT, *h, *w, *upd;
  cudaGetSymbolAddress((void**)&w1T, g_w1T);
  cudaGetSymbolAddress((void**)&wuT, g_wuT);
  cudaGetSymbolAddress((void**)&refT, g_refT);
  cudaGetSymbolAddress((void**)&h, g_h);
  cudaGetSymbolAddress((void**)&w, g_w);
  cudaGetSymbolAddress((void**)&upd, g_upd);

  dim3 tb(32, 8);
  k_transpose<<<dim3(128 / 32, 512 / 32), tb>>>(W1, w1T, 512, 128);
  k_transpose<<<dim3(512 / 32, 1024 / 32), tb>>>(WU, wuT, 1024, 512);
  k_transpose<<<dim3(512 / 32, 64 / 32), tb>>>(REF, refT, 64, 512);

  // K1: h = relu(X @ W1 + b1)
  gemm_mma<1, 512, false><<<dim3(1, NB / 128), 256>>>(X, nullptr, 512, w1T, b1, h, 128);
  // K2: softmax weights
  k2_softmax<<<NB / 64, 256>>>(W2, b2);
  // K3: selected = w @ ref
  gemm_mma<0, 64, false><<<dim3(4, NB / 128), 256>>>(w, nullptr, 64, refT, nullptr, out_sel, 512);
  // K4: updates = tanh([X | selected] @ Wu + bu)
  gemm_mma<2, 1024, true><<<dim3(4, NB / 128), 256>>>(X, out_sel, 512, wuT, bu, upd, 512);
  // K5: ref update (deterministic split-K)
  k5a_partials<<<NCHUNK * 4, 256>>>();
  k5b_reduce<<<(NS * ND) / 256, 256>>>(REF, out_ref);
}

// round 6
// speedup vs baseline: 3.0181x; 1.1217x over previous
#include <cuda_runtime.h>
#include <math.h>
#include <stdint.h>

#define NB 131072
#define ND 512
#define NS 64
#define NH 128
#define NCHUNK 128
#define CHUNK_ROWS (NB / NCHUNK)   /* 1024 */

// ---- scratch (static device globals; no runtime allocation) ----
static __device__ float g_h[(size_t)NB * NH];             // relu hidden
static __device__ float g_w[(size_t)NB * NS];             // softmax weights (tf32-rounded)
static __device__ float g_upd[(size_t)NB * ND];           // tanh updates (tf32-rounded)
static __device__ float g_part[(size_t)NCHUNK * NS * ND]; // split-K partials
static __device__ float g_w1T[(size_t)NH * ND];           // [128][512] tf32
static __device__ float g_wuT[(size_t)ND * 2 * ND];       // [512][1024] tf32
static __device__ float g_refT[(size_t)ND * NS];          // [512][64] tf32

// ============================================================
// helpers
// ============================================================
__device__ __forceinline__ float f2tf32f(float x) {
  uint32_t r;
  asm("cvt.rna.tf32.f32 %0, %1;" : "=r"(r) : "f"(x));
  return __uint_as_float(r);
}
__device__ __forceinline__ void mma_tf32(float c[4], const uint32_t a[4],
                                         const uint32_t b[2]) {
  asm volatile(
      "mma.sync.aligned.m16n8k8.row.col.f32.tf32.tf32.f32 "
      "{%0,%1,%2,%3}, {%4,%5,%6,%7}, {%8,%9}, {%0,%1,%2,%3};"
      : "+f"(c[0]), "+f"(c[1]), "+f"(c[2]), "+f"(c[3])
      : "r"(a[0]), "r"(a[1]), "r"(a[2]), "r"(a[3]), "r"(b[0]), "r"(b[1]));
}
template <int ACT> __device__ __forceinline__ float actf(float x) {
  if (ACT == 1) return x > 0.f ? x : 0.f;
  if (ACT == 2) return tanhf(x);
  return x;
}
#define CP_A16(dst, src)                                              \
  asm volatile("cp.async.cg.shared.global [%0], [%1], 16;"            \
               :: "r"(dst), "l"(__cvta_generic_to_global(src)) : "memory")
#define CP_COMMIT() asm volatile("cp.async.commit_group;" ::: "memory")
#define CP_WAIT0() asm volatile("cp.async.wait_group 0;" ::: "memory")
#define CP_WAIT1() asm volatile("cp.async.wait_group 1;" ::: "memory")

__device__ __forceinline__ uint32_t smem_u32(const void* p) {
  uint32_t a;
  asm("{ .reg .u64 t; cvta.to.shared.u64 t, %1; cvt.u32.u64 %0, t; }"
      : "=r"(a) : "l"(p));
  return a;
}

// ============================================================
// generic 32x32 transpose + tf32 round: dst[C][R] = tf32(src[R][C]^T)
// ============================================================
__global__ void k_transpose(const float* __restrict__ src, float* __restrict__ dst,
                            int R, int C) {
  __shared__ float t[32][33];
  int c0 = blockIdx.x * 32, r0 = blockIdx.y * 32;
  int x = threadIdx.x, y = threadIdx.y;
#pragma unroll
  for (int i = 0; i < 32; i += 8)
    t[y + i][x] = src[(size_t)(r0 + y + i) * C + c0 + x];
  __syncthreads();
#pragma unroll
  for (int i = 0; i < 32; i += 8)
    dst[(size_t)(c0 + y + i) * R + r0 + x] = f2tf32f(t[x][y + i]);
}

// ============================================================
// tf32 mma.sync GEMM, cp.async 2-stage pipeline:
//   OUT[m, n] = ACT( sum_k A[m,k]*BT[n,k] + bias[n] )
// CTA tile 128x128, BK=16; 8 warps 4(m) x 2(n); warp tile 32x64.
// BT assumed tf32-rounded at source; A converted in-consumer iff CVT_A.
// ============================================================
template <int ACT, int KTOT, bool ASPLIT, bool CVT_A>
__global__ __launch_bounds__(256, 2) void gemm_mma(
    const float* __restrict__ A0, const float* __restrict__ A1, int a_stride,
    const float* __restrict__ BT, const float* __restrict__ bias,
    float* __restrict__ OUT, int o_stride) {
  __shared__ float As[2][128][20];
  __shared__ float Bs[2][128][20];
  const int tid = threadIdx.x, wid = tid >> 5, lane = tid & 31;
  const int n0 = blockIdx.x * 128;
  const int m0 = blockIdx.y * 128;
  const int wm = (wid & 3) * 32;
  const int wn = (wid >> 2) * 64;
  const int g = lane >> 2, t = lane & 3;

  const uint32_t sA = smem_u32(&As[0][0][0]);
  const uint32_t sB = smem_u32(&Bs[0][0][0]);
  const int row_l = tid >> 2;           // 0..63 (l adds 64)
  const int c4_l = (tid & 3) * 4;       // 0,4,8,12

  float acc[2][8][4];
#pragma unroll
  for (int mt = 0; mt < 2; mt++)
#pragma unroll
    for (int nt = 0; nt < 8; nt++)
#pragma unroll
      for (int r = 0; r < 4; r++) acc[mt][nt][r] = 0.f;

  auto load_tiles = [&](int c, int buf) {
    const int k0 = c * 16;
    const float* Asrc = (!ASPLIT || k0 < 512) ? A0 : A1;
    const int ko = (!ASPLIT || k0 < 512) ? k0 : k0 - 512;
    const uint32_t da = sA + (uint32_t)buf * (128 * 20 * 4);
    const uint32_t db = sB + (uint32_t)buf * (128 * 20 * 4);
#pragma unroll
    for (int l = 0; l < 2; l++) {
      const int row = row_l + l * 64;
      CP_A16(da + (uint32_t)(row * 20 + c4_l) * 4,
             Asrc + (size_t)(m0 + row) * a_stride + ko + c4_l);
      CP_A16(db + (uint32_t)(row * 20 + c4_l) * 4,
             BT + (size_t)(n0 + row) * KTOT + k0 + c4_l);
    }
  };

  constexpr int NCH = KTOT / 16;
  load_tiles(0, 0);
  CP_COMMIT();
#pragma unroll 1
  for (int c = 0; c < NCH; c++) {
    const int buf = c & 1;
    if (c + 1 < NCH) {
      load_tiles(c + 1, buf ^ 1);
      CP_COMMIT();
      CP_WAIT1();
    } else {
      CP_WAIT0();
    }
    __syncthreads();
#pragma unroll
    for (int ks = 0; ks < 2; ks++) {
      const int kk = ks * 8;
      uint32_t a[2][4], b[8][2];
#pragma unroll
      for (int mt = 0; mt < 2; mt++) {
        const int rb = wm + mt * 16;
        float a0 = As[buf][rb + g][kk + t];
        float a1 = As[buf][rb + 8 + g][kk + t];
        float a2 = As[buf][rb + g][kk + t + 4];
        float a3 = As[buf][rb + 8 + g][kk + t + 4];
        if (CVT_A) { a0 = f2tf32f(a0); a1 = f2tf32f(a1); a2 = f2tf32f(a2); a3 = f2tf32f(a3); }
        a[mt][0] = __float_as_uint(a0); a[mt][1] = __float_as_uint(a1);
        a[mt][2] = __float_as_uint(a2); a[mt][3] = __float_as_uint(a3);
      }
#pragma unroll
      for (int nt = 0; nt < 8; nt++) {
        const int nb = wn + nt * 8;
        b[nt][0] = __float_as_uint(Bs[buf][nb + g][kk + t]);
        b[nt][1] = __float_as_uint(Bs[buf][nb + g][kk + t + 4]);
      }
#pragma unroll
      for (int mt = 0; mt < 2; mt++)
#pragma unroll
        for (int nt = 0; nt < 8; nt++) mma_tf32(acc[mt][nt], a[mt], b[nt]);
    }
    __syncthreads();
  }

  // epilogue: lane owns rows {g, g+8}, cols {t*2, t*2+1} per tile
#pragma unroll
  for (int mt = 0; mt < 2; mt++) {
#pragma unroll
    for (int nt = 0; nt < 8; nt++) {
      const int row = m0 + wm + mt * 16 + g;
      const int col = n0 + wn + nt * 8 + t * 2;
      float b0 = 0.f, b1 = 0.f;
      if (bias) { b0 = bias[col]; b1 = bias[col + 1]; }
      float r0 = actf<ACT>(acc[mt][nt][0] + b0);
      float r1 = actf<ACT>(acc[mt][nt][1] + b1);
      float r2 = actf<ACT>(acc[mt][nt][2] + b0);
      float r3 = actf<ACT>(acc[mt][nt][3] + b1);
      if (ACT == 2) { r0 = f2tf32f(r0); r1 = f2tf32f(r1); r2 = f2tf32f(r2); r3 = f2tf32f(r3); }
      *(float2*)(OUT + (size_t)row * o_stride + col) = make_float2(r0, r1);
      *(float2*)(OUT + (size_t)(row + 8) * o_stride + col) = make_float2(r2, r3);
    }
  }
}

// ============================================================
// K2: logits = h @ W2 + b2 ; w = softmax(logits); store tf32-rounded
// ============================================================
__global__ __launch_bounds__(256) void k2_softmax(
    const float* __restrict__ W2, const float* __restrict__ b2) {
  __shared__ __align__(16) float w2s[128 * 64];
  __shared__ __align__(16) float hs[8][128];
  __shared__ float b2s[64];
  const int tid = threadIdx.x;
  for (int i = tid; i < (128 * 64) / 4; i += 256)
    ((float4*)w2s)[i] = ((const float4*)W2)[i];
  if (tid < 64) b2s[tid] = b2[tid];
  __syncthreads();

  const int warp = tid >> 5, lane = tid & 31;
  const int row_base = blockIdx.x * 64 + warp * 8;
  for (int r = 0; r < 8; r++) {
    int row = row_base + r;
    ((float4*)hs[warp])[lane] = ((const float4*)(g_h + (size_t)row * 128))[lane];
    __syncwarp();
    float a0 = b2s[lane], a1 = b2s[lane + 32];
#pragma unroll 8
    for (int k = 0; k < 128; k++) {
      float hk = hs[warp][k];
      a0 = fmaf(hk, w2s[k * 64 + lane], a0);
      a1 = fmaf(hk, w2s[k * 64 + lane + 32], a1);
    }
    float m = fmaxf(a0, a1);
#pragma unroll
    for (int o = 16; o > 0; o >>= 1) m = fmaxf(m, __shfl_xor_sync(~0u, m, o));
    float e0 = __expf(a0 - m), e1 = __expf(a1 - m);
    float s = e0 + e1;
#pragma unroll
    for (int o = 16; o > 0; o >>= 1) s += __shfl_xor_sync(~0u, s, o);
    float inv = 1.f / s;
    g_w[(size_t)row * 64 + lane]      = f2tf32f(e0 * inv);
    g_w[(size_t)row * 64 + lane + 32] = f2tf32f(e1 * inv);
    __syncwarp();
  }
}

// ============================================================
// K5a: split-K partials of w^T @ updates via tf32 mma (both operands
// tf32-rounded at source). C tile [64 s x 128 d]; warps 2(s) x 4(d).
// ============================================================
__global__ __launch_bounds__(256) void k5a_partials() {
  const int dq    = blockIdx.x & 3;
  const int chunk = blockIdx.x >> 2;
  const int d0 = dq * 128;
  const int b0 = chunk * CHUNK_ROWS;
  __shared__ float wt[2][16][68];
  __shared__ float ut[2][16][132];
  const int tid = threadIdx.x, wid = tid >> 5, lane = tid & 31;
  const int sw = (wid & 1) * 32, dw = (wid >> 1) * 32;
  const int g = lane >> 2, t = lane & 3;
  const uint32_t sW = smem_u32(&wt[0][0][0]);
  const uint32_t sU = smem_u32(&ut[0][0][0]);

  float acc[2][4][4];
#pragma unroll
  for (int mt = 0; mt < 2; mt++)
#pragma unroll
    for (int nt = 0; nt < 4; nt++)
#pragma unroll
      for (int r = 0; r < 4; r++) acc[mt][nt][r] = 0.f;

  auto load = [&](int c, int buf) {
    const int k0 = c * 16;
    {
      const int row = tid >> 4, c4 = (tid & 15) * 4;
      CP_A16(sW + (uint32_t)buf * (16 * 68 * 4) + (uint32_t)(row * 68 + c4) * 4,
             g_w + (size_t)(b0 + k0 + row) * 64 + c4);
    }
#pragma unroll
    for (int l = 0; l < 2; l++) {
      const int lin = tid + l * 256;
      const int row = lin >> 5, c4 = (lin & 31) * 4;
      CP_A16(sU + (uint32_t)buf * (16 * 132 * 4) + (uint32_t)(row * 132 + c4) * 4,
             g_upd + (size_t)(b0 + k0 + row) * 512 + d0 + c4);
    }
  };

  constexpr int NCH = CHUNK_ROWS / 16;
  load(0, 0);
  CP_COMMIT();
#pragma unroll 1
  for (int c = 0; c < NCH; c++) {
    const int buf = c & 1;
    if (c + 1 < NCH) { load(c + 1, buf ^ 1); CP_COMMIT(); CP_WAIT1(); }
    else CP_WAIT0();
    __syncthreads();
#pragma unroll
    for (int ks = 0; ks < 2; ks++) {
      const int kk = ks * 8;
      uint32_t a[2][4], b[4][2];
#pragma unroll
      for (int mt = 0; mt < 2; mt++) {
        const int sb = sw + mt * 16;
        a[mt][0] = __float_as_uint(wt[buf][kk + t][sb + g]);
        a[mt][1] = __float_as_uint(wt[buf][kk + t][sb + 8 + g]);
        a[mt][2] = __float_as_uint(wt[buf][kk + t + 4][sb + g]);
        a[mt][3] = __float_as_uint(wt[buf][kk + t + 4][sb + 8 + g]);
      }
#pragma unroll
      for (int nt = 0; nt < 4; nt++) {
        const int db = dw + nt * 8;
        b[nt][0] = __float_as_uint(ut[buf][kk + t][db + g]);
        b[nt][1] = __float_as_uint(ut[buf][kk + t + 4][db + g]);
      }
#pragma unroll
      for (int mt = 0; mt < 2; mt++)
#pragma unroll
        for (int nt = 0; nt < 4; nt++) mma_tf32(acc[mt][nt], a[mt], b[nt]);
    }
    __syncthreads();
  }

  float* p = g_part + (size_t)chunk * (NS * ND);
#pragma unroll
  for (int mt = 0; mt < 2; mt++) {
#pragma unroll
    for (int nt = 0; nt < 4; nt++) {
      const int s = sw + mt * 16 + g;
      const int d = d0 + dw + nt * 8 + t * 2;
      *(float2*)(p + (size_t)s * 512 + d) = make_float2(acc[mt][nt][0], acc[mt][nt][1]);
      *(float2*)(p + (size_t)(s + 8) * 512 + d) = make_float2(acc[mt][nt][2], acc[mt][nt][3]);
    }
  }
}

// ============================================================
// K5b: new_ref = ref + 0.01 * sum(partials)   (deterministic order)
// ============================================================
__global__ __launch_bounds__(256) void k5b_reduce(
    const float* __restrict__ REF, float* __restrict__ OUT_REF) {
  const int idx = blockIdx.x * 256 + threadIdx.x;
  float s = 0.f;
#pragma unroll 8
  for (int c = 0; c < NCHUNK; c++) s += g_part[(size_t)c * (NS * ND) + idx];
  OUT_REF[idx] = REF[idx] + 0.01f * s;
}

// ============================================================
extern "C" void kernel_launch(void* const* d_in, const int* in_sizes, int n_in,
                              void* d_out, int out_size) {
  const float* X   = (const float*)d_in[0];
  const float* REF = (const float*)d_in[1];
  const float* W1  = (const float*)d_in[2];
  const float* b1  = (const float*)d_in[3];
  const float* W2  = (const float*)d_in[4];
  const float* b2  = (const float*)d_in[5];
  const float* WU  = (const float*)d_in[6];
  const float* bu  = (const float*)d_in[7];

  float* out_sel = (float*)d_out;
  float* out_ref = (float*)d_out + (size_t)NB * ND;

  float *w1T, *wuT, *refT, *h, *w, *upd;
  cudaGetSymbolAddress((void**)&w1T, g_w1T);
  cudaGetSymbolAddress((void**)&wuT, g_wuT);
  cudaGetSymbolAddress((void**)&refT, g_refT);
  cudaGetSymbolAddress((void**)&h, g_h);
  cudaGetSymbolAddress((void**)&w, g_w);
  cudaGetSymbolAddress((void**)&upd, g_upd);

  dim3 tb(32, 8);
  k_transpose<<<dim3(128 / 32, 512 / 32), tb>>>(W1, w1T, 512, 128);
  k_transpose<<<dim3(512 / 32, 1024 / 32), tb>>>(WU, wuT, 1024, 512);
  k_transpose<<<dim3(512 / 32, 64 / 32), tb>>>(REF, refT, 64, 512);

  // K1: h = relu(X @ W1 + b1)
  gemm_mma<1, 512, false, true><<<dim3(1, NB / 128), 256>>>(X, nullptr, 512, w1T, b1, h, 128);
  // K2: softmax weights (tf32-rounded at store)
  k2_softmax<<<NB / 64, 256>>>(W2, b2);
  // K3: selected = w @ ref  (A already tf32)
  gemm_mma<0, 64, false, false><<<dim3(4, NB / 128), 256>>>(w, nullptr, 64, refT, nullptr, out_sel, 512);
  // K4: updates = tanh([X | selected] @ Wu + bu), tf32-rounded at store
  gemm_mma<2, 1024, true, true><<<dim3(4, NB / 128), 256>>>(X, out_sel, 512, wuT, bu, upd, 512);
  // K5: ref update (deterministic split-K, tensor-core)
  k5a_partials<<<NCHUNK * 4, 256>>>();
  k5b_reduce<<<(NS * ND) / 256, 256>>>(REF, out_ref);
}

// round 8
// speedup vs baseline: 4.6266x; 1.5330x over previous
#include <cuda_runtime.h>
#include <math.h>
#include <stdint.h>

#define NB 131072
#define ND 512
#define NS 64
#define NH 128
#define NCHUNK 128
#define CHUNK_ROWS (NB / NCHUNK)   /* 1024 */

// ---- scratch (static device globals; no runtime allocation) ----
static __device__ float g_h[(size_t)NB * NH];             // relu hidden (tf32-rounded)
static __device__ float g_w[(size_t)NB * NS];             // softmax weights (tf32-rounded)
static __device__ float g_upd[(size_t)NB * ND];           // tanh updates (tf32-rounded)
static __device__ float g_part[(size_t)NCHUNK * NS * ND]; // split-K partials
static __device__ float g_w1T[(size_t)NH * ND];           // [128][512] tf32
static __device__ float g_refT[(size_t)ND * NS];          // [512][64] tf32
static __device__ float g_w2T[(size_t)NS * NH];           // [64][128] tf32
static __device__ float g_bt[(size_t)ND * 576];           // [512 n][576 k] = [Wu1^T | RW^T] tf32
static __device__ float g_rw[(size_t)NS * ND];            // RW = ref @ Wu2  [64][512] f32

// ============================================================
// helpers
// ============================================================
__device__ __forceinline__ float f2tf32f(float x) {
  uint32_t r;
  asm("cvt.rna.tf32.f32 %0, %1;" : "=r"(r) : "f"(x));
  return __uint_as_float(r);
}
__device__ __forceinline__ void mma_tf32(float c[4], const uint32_t a[4],
                                         const uint32_t b[2]) {
  asm volatile(
      "mma.sync.aligned.m16n8k8.row.col.f32.tf32.tf32.f32 "
      "{%0,%1,%2,%3}, {%4,%5,%6,%7}, {%8,%9}, {%0,%1,%2,%3};"
      : "+f"(c[0]), "+f"(c[1]), "+f"(c[2]), "+f"(c[3])
      : "r"(a[0]), "r"(a[1]), "r"(a[2]), "r"(a[3]), "r"(b[0]), "r"(b[1]));
}
template <int ACT> __device__ __forceinline__ float actf(float x) {
  if (ACT == 1) return x > 0.f ? x : 0.f;
  if (ACT == 2) return tanhf(x);
  return x;
}
#define CP_A16(dst, src)                                              \
  asm volatile("cp.async.cg.shared.global [%0], [%1], 16;"            \
               :: "r"(dst), "l"(__cvta_generic_to_global(src)) : "memory")
#define CP_COMMIT() asm volatile("cp.async.commit_group;" ::: "memory")
#define CP_WAIT0() asm volatile("cp.async.wait_group 0;" ::: "memory")
#define CP_WAIT1() asm volatile("cp.async.wait_group 1;" ::: "memory")

__device__ __forceinline__ uint32_t smem_u32(const void* p) {
  uint32_t a;
  asm("{ .reg .u64 t; cvta.to.shared.u64 t, %1; cvt.u32.u64 %0, t; }"
      : "=r"(a) : "l"(p));
  return a;
}

// ============================================================
// 32x32 transpose + tf32 round: dst[c*dst_stride + r] = tf32(src[r][c])
// grid: (C/32, R/32)
// ============================================================
__global__ void k_transpose(const float* __restrict__ src, float* __restrict__ dst,
                            int R, int C, int dst_stride) {
  __shared__ float t[32][33];
  int c0 = blockIdx.x * 32, r0 = blockIdx.y * 32;
  int x = threadIdx.x, y = threadIdx.y;
#pragma unroll
  for (int i = 0; i < 32; i += 8)
    t[y + i][x] = src[(size_t)(r0 + y + i) * C + c0 + x];
  __syncthreads();
#pragma unroll
  for (int i = 0; i < 32; i += 8)
    dst[(size_t)(c0 + y + i) * dst_stride + r0 + x] = f2tf32f(t[x][y + i]);
}

// ============================================================
// RW = ref @ Wu2  (f32 FFMA; tiny: 64x512x512)
// grid = 8 (n-blocks of 64), block 256
// ============================================================
__global__ __launch_bounds__(256) void k_rw(
    const float* __restrict__ REF, const float* __restrict__ WU,
    float* __restrict__ RW) {
  __shared__ float rs[64][17];
  __shared__ float us[16][68];
  const int tid = threadIdx.x;
  const int n0 = blockIdx.x * 64;
  const int si = (tid >> 4) * 4, ni = (tid & 15) * 4;
  float acc[4][4];
#pragma unroll
  for (int i = 0; i < 4; i++)
#pragma unroll
    for (int j = 0; j < 4; j++) acc[i][j] = 0.f;

  for (int k0 = 0; k0 < 512; k0 += 16) {
    {
      int s = tid >> 2, c4 = (tid & 3) * 4;
      float4 v = *(const float4*)(REF + (size_t)s * 512 + k0 + c4);
      rs[s][c4] = v.x; rs[s][c4 + 1] = v.y; rs[s][c4 + 2] = v.z; rs[s][c4 + 3] = v.w;
    }
    {
      int r = tid >> 4, c4 = (tid & 15) * 4;
      float4 v = *(const float4*)(WU + (size_t)(512 + k0 + r) * 512 + n0 + c4);
      us[r][c4] = v.x; us[r][c4 + 1] = v.y; us[r][c4 + 2] = v.z; us[r][c4 + 3] = v.w;
    }
    __syncthreads();
#pragma unroll
    for (int kk = 0; kk < 16; kk++) {
#pragma unroll
      for (int i = 0; i < 4; i++) {
        float r = rs[si + i][kk];
#pragma unroll
        for (int j = 0; j < 4; j++) acc[i][j] = fmaf(r, us[kk][ni + j], acc[i][j]);
      }
    }
    __syncthreads();
  }
#pragma unroll
  for (int i = 0; i < 4; i++)
#pragma unroll
    for (int j = 0; j < 4; j++)
      RW[(size_t)(si + i) * 512 + n0 + ni + j] = acc[i][j];
}

// ============================================================
// tf32 mma.sync GEMM, cp.async 2-stage pipeline:
//   OUT[m, n] = ACT( sum_k A[m,k]*BT[n,k] + bias[n] )
// CTA tile 128x128, BK=16; 8 warps 4(m) x 2(n); warp tile 32x64.
// A split at k=512 (A1, a1_stride) iff ASPLIT. Outputs tf32-rounded
// for ACT!=0 (scratch consumed by later mma kernels).
// ============================================================
template <int ACT, int KTOT, bool ASPLIT, bool CVT_A>
__global__ __launch_bounds__(256, 2) void gemm_mma(
    const float* __restrict__ A0, const float* __restrict__ A1,
    int a_stride, int a1_stride,
    const float* __restrict__ BT, const float* __restrict__ bias,
    float* __restrict__ OUT, int o_stride) {
  __shared__ float As[2][128][20];
  __shared__ float Bs[2][128][20];
  const int tid = threadIdx.x, wid = tid >> 5, lane = tid & 31;
  const int n0 = blockIdx.x * 128;
  const int m0 = blockIdx.y * 128;
  const int wm = (wid & 3) * 32;
  const int wn = (wid >> 2) * 64;
  const int g = lane >> 2, t = lane & 3;

  const uint32_t sA = smem_u32(&As[0][0][0]);
  const uint32_t sB = smem_u32(&Bs[0][0][0]);
  const int row_l = tid >> 2;
  const int c4_l = (tid & 3) * 4;

  float acc[2][8][4];
#pragma unroll
  for (int mt = 0; mt < 2; mt++)
#pragma unroll
    for (int nt = 0; nt < 8; nt++)
#pragma unroll
      for (int r = 0; r < 4; r++) acc[mt][nt][r] = 0.f;

  auto load_tiles = [&](int c, int buf) {
    const int k0 = c * 16;
    const float* Asrc = (!ASPLIT || k0 < 512) ? A0 : A1;
    const int ko = (!ASPLIT || k0 < 512) ? k0 : k0 - 512;
    const int ast = (!ASPLIT || k0 < 512) ? a_stride : a1_stride;
    const uint32_t da = sA + (uint32_t)buf * (128 * 20 * 4);
    const uint32_t db = sB + (uint32_t)buf * (128 * 20 * 4);
#pragma unroll
    for (int l = 0; l < 2; l++) {
      const int row = row_l + l * 64;
      CP_A16(da + (uint32_t)(row * 20 + c4_l) * 4,
             Asrc + (size_t)(m0 + row) * ast + ko + c4_l);
      CP_A16(db + (uint32_t)(row * 20 + c4_l) * 4,
             BT + (size_t)(n0 + row) * KTOT + k0 + c4_l);
    }
  };

  constexpr int NCH = KTOT / 16;
  load_tiles(0, 0);
  CP_COMMIT();
#pragma unroll 1
  for (int c = 0; c < NCH; c++) {
    const int buf = c & 1;
    if (c + 1 < NCH) {
      load_tiles(c + 1, buf ^ 1);
      CP_COMMIT();
      CP_WAIT1();
    } else {
      CP_WAIT0();
    }
    __syncthreads();
#pragma unroll
    for (int ks = 0; ks < 2; ks++) {
      const int kk = ks * 8;
      uint32_t a[2][4], b[8][2];
#pragma unroll
      for (int mt = 0; mt < 2; mt++) {
        const int rb = wm + mt * 16;
        float a0 = As[buf][rb + g][kk + t];
        float a1 = As[buf][rb + 8 + g][kk + t];
        float a2 = As[buf][rb + g][kk + t + 4];
        float a3 = As[buf][rb + 8 + g][kk + t + 4];
        if (CVT_A) { a0 = f2tf32f(a0); a1 = f2tf32f(a1); a2 = f2tf32f(a2); a3 = f2tf32f(a3); }
        a[mt][0] = __float_as_uint(a0); a[mt][1] = __float_as_uint(a1);
        a[mt][2] = __float_as_uint(a2); a[mt][3] = __float_as_uint(a3);
      }
#pragma unroll
      for (int nt = 0; nt < 8; nt++) {
        const int nb = wn + nt * 8;
        b[nt][0] = __float_as_uint(Bs[buf][nb + g][kk + t]);
        b[nt][1] = __float_as_uint(Bs[buf][nb + g][kk + t + 4]);
      }
#pragma unroll
      for (int mt = 0; mt < 2; mt++)
#pragma unroll
        for (int nt = 0; nt < 8; nt++) mma_tf32(acc[mt][nt], a[mt], b[nt]);
    }
    __syncthreads();
  }

#pragma unroll
  for (int mt = 0; mt < 2; mt++) {
#pragma unroll
    for (int nt = 0; nt < 8; nt++) {
      const int row = m0 + wm + mt * 16 + g;
      const int col = n0 + wn + nt * 8 + t * 2;
      float b0 = 0.f, b1 = 0.f;
      if (bias) { b0 = bias[col]; b1 = bias[col + 1]; }
      float r0 = actf<ACT>(acc[mt][nt][0] + b0);
      float r1 = actf<ACT>(acc[mt][nt][1] + b1);
      float r2 = actf<ACT>(acc[mt][nt][2] + b0);
      float r3 = actf<ACT>(acc[mt][nt][3] + b1);
      if (ACT != 0) { r0 = f2tf32f(r0); r1 = f2tf32f(r1); r2 = f2tf32f(r2); r3 = f2tf32f(r3); }
      *(float2*)(OUT + (size_t)row * o_stride + col) = make_float2(r0, r1);
      *(float2*)(OUT + (size_t)(row + 8) * o_stride + col) = make_float2(r2, r3);
    }
  }
}

// ============================================================
// K2: w = softmax(h @ W2 + b2) via tf32 mma, softmax in registers.
// CTA: 128 rows; 8 warps, warp = 16 rows x 64 cols; K=128, BK=16.
// ============================================================
__global__ __launch_bounds__(256, 2) void k2_mma(
    const float* __restrict__ W2T, const float* __restrict__ b2) {
  __shared__ float As[2][128][20];
  __shared__ float Bs[2][64][20];
  const int tid = threadIdx.x, wid = tid >> 5, lane = tid & 31;
  const int m0 = blockIdx.x * 128;
  const int g = lane >> 2, t = lane & 3;
  const uint32_t sA = smem_u32(&As[0][0][0]);
  const uint32_t sB = smem_u32(&Bs[0][0][0]);

  float acc[8][4];
#pragma unroll
  for (int nt = 0; nt < 8; nt++)
#pragma unroll
    for (int r = 0; r < 4; r++) acc[nt][r] = 0.f;

  auto load = [&](int c, int buf) {
    const int k0 = c * 16;
    const int rowa = tid >> 2, c4 = (tid & 3) * 4;
#pragma unroll
    for (int l = 0; l < 2; l++) {
      const int row = rowa + l * 64;
      CP_A16(sA + (uint32_t)buf * (128 * 20 * 4) + (uint32_t)(row * 20 + c4) * 4,
             g_h + (size_t)(m0 + row) * 128 + k0 + c4);
    }
    if (rowa < 64)
      CP_A16(sB + (uint32_t)buf * (64 * 20 * 4) + (uint32_t)(rowa * 20 + c4) * 4,
             W2T + (size_t)rowa * 128 + k0 + c4);
  };

  load(0, 0);
  CP_COMMIT();
#pragma unroll 1
  for (int c = 0; c < 8; c++) {
    const int buf = c & 1;
    if (c + 1 < 8) { load(c + 1, buf ^ 1); CP_COMMIT(); CP_WAIT1(); }
    else CP_WAIT0();
    __syncthreads();
#pragma unroll
    for (int ks = 0; ks < 2; ks++) {
      const int kk = ks * 8;
      uint32_t a[4], b[8][2];
      const int rb = wid * 16;
      a[0] = __float_as_uint(As[buf][rb + g][kk + t]);
      a[1] = __float_as_uint(As[buf][rb + 8 + g][kk + t]);
      a[2] = __float_as_uint(As[buf][rb + g][kk + t + 4]);
      a[3] = __float_as_uint(As[buf][rb + 8 + g][kk + t + 4]);
#pragma unroll
      for (int nt = 0; nt < 8; nt++) {
        b[nt][0] = __float_as_uint(Bs[buf][nt * 8 + g][kk + t]);
        b[nt][1] = __float_as_uint(Bs[buf][nt * 8 + g][kk + t + 4]);
      }
#pragma unroll
      for (int nt = 0; nt < 8; nt++) mma_tf32(acc[nt], a, b[nt]);
    }
    __syncthreads();
  }

  // add bias
#pragma unroll
  for (int nt = 0; nt < 8; nt++) {
    float2 bb = *(const float2*)(b2 + nt * 8 + t * 2);
    acc[nt][0] += bb.x; acc[nt][1] += bb.y;
    acc[nt][2] += bb.x; acc[nt][3] += bb.y;
  }
  // softmax per row: row r0 -> acc[*][0,1]; row r0+8 -> acc[*][2,3]
  float m0v = -1e30f, m1v = -1e30f;
#pragma unroll
  for (int nt = 0; nt < 8; nt++) {
    m0v = fmaxf(m0v, fmaxf(acc[nt][0], acc[nt][1]));
    m1v = fmaxf(m1v, fmaxf(acc[nt][2], acc[nt][3]));
  }
#pragma unroll
  for (int o = 1; o <= 2; o <<= 1) {
    m0v = fmaxf(m0v, __shfl_xor_sync(~0u, m0v, o));
    m1v = fmaxf(m1v, __shfl_xor_sync(~0u, m1v, o));
  }
  float s0 = 0.f, s1 = 0.f;
#pragma unroll
  for (int nt = 0; nt < 8; nt++) {
    acc[nt][0] = __expf(acc[nt][0] - m0v); s0 += acc[nt][0];
    acc[nt][1] = __expf(acc[nt][1] - m0v); s0 += acc[nt][1];
    acc[nt][2] = __expf(acc[nt][2] - m1v); s1 += acc[nt][2];
    acc[nt][3] = __expf(acc[nt][3] - m1v); s1 += acc[nt][3];
  }
#pragma unroll
  for (int o = 1; o <= 2; o <<= 1) {
    s0 += __shfl_xor_sync(~0u, s0, o);
    s1 += __shfl_xor_sync(~0u, s1, o);
  }
  const float i0 = 1.f / s0, i1 = 1.f / s1;
  const int r0 = m0 + wid * 16 + g;
#pragma unroll
  for (int nt = 0; nt < 8; nt++) {
    const int col = nt * 8 + t * 2;
    *(float2*)(g_w + (size_t)r0 * 64 + col) =
        make_float2(f2tf32f(acc[nt][0] * i0), f2tf32f(acc[nt][1] * i0));
    *(float2*)(g_w + (size_t)(r0 + 8) * 64 + col) =
        make_float2(f2tf32f(acc[nt][2] * i1), f2tf32f(acc[nt][3] * i1));
  }
}

// ============================================================
// K5a: split-K partials of w^T @ updates via tf32 mma.
// C tile [64 s x 128 d]; warps 2(s) x 4(d).
// ============================================================
__global__ __launch_bounds__(256) void k5a_partials() {
  const int dq    = blockIdx.x & 3;
  const int chunk = blockIdx.x >> 2;
  const int d0 = dq * 128;
  const int b0 = chunk * CHUNK_ROWS;
  __shared__ float wt[2][16][68];
  __shared__ float ut[2][16][132];
  const int tid = threadIdx.x, wid = tid >> 5, lane = tid & 31;
  const int sw = (wid & 1) * 32, dw = (wid >> 1) * 32;
  const int g = lane >> 2, t = lane & 3;
  const uint32_t sW = smem_u32(&wt[0][0][0]);
  const uint32_t sU = smem_u32(&ut[0][0][0]);

  float acc[2][4][4];
#pragma unroll
  for (int mt = 0; mt < 2; mt++)
#pragma unroll
    for (int nt = 0; nt < 4; nt++)
#pragma unroll
      for (int r = 0; r < 4; r++) acc[mt][nt][r] = 0.f;

  auto load = [&](int c, int buf) {
    const int k0 = c * 16;
    {
      const int row = tid >> 4, c4 = (tid & 15) * 4;
      CP_A16(sW + (uint32_t)buf * (16 * 68 * 4) + (uint32_t)(row * 68 + c4) * 4,
             g_w + (size_t)(b0 + k0 + row) * 64 + c4);
    }
#pragma unroll
    for (int l = 0; l < 2; l++) {
      const int lin = tid + l * 256;
      const int row = lin >> 5, c4 = (lin & 31) * 4;
      CP_A16(sU + (uint32_t)buf * (16 * 132 * 4) + (uint32_t)(row * 132 + c4) * 4,
             g_upd + (size_t)(b0 + k0 + row) * 512 + d0 + c4);
    }
  };

  constexpr int NCH = CHUNK_ROWS / 16;
  load(0, 0);
  CP_COMMIT();
#pragma unroll 1
  for (int c = 0; c < NCH; c++) {
    const int buf = c & 1;
    if (c + 1 < NCH) { load(c + 1, buf ^ 1); CP_COMMIT(); CP_WAIT1(); }
    else CP_WAIT0();
    __syncthreads();
#pragma unroll
    for (int ks = 0; ks < 2; ks++) {
      const int kk = ks * 8;
      uint32_t a[2][4], b[4][2];
#pragma unroll
      for (int mt = 0; mt < 2; mt++) {
        const int sb = sw + mt * 16;
        a[mt][0] = __float_as_uint(wt[buf][kk + t][sb + g]);
        a[mt][1] = __float_as_uint(wt[buf][kk + t][sb + 8 + g]);
        a[mt][2] = __float_as_uint(wt[buf][kk + t + 4][sb + g]);
        a[mt][3] = __float_as_uint(wt[buf][kk + t + 4][sb + 8 + g]);
      }
#pragma unroll
      for (int nt = 0; nt < 4; nt++) {
        const int db = dw + nt * 8;
        b[nt][0] = __float_as_uint(ut[buf][kk + t][db + g]);
        b[nt][1] = __float_as_uint(ut[buf][kk + t + 4][db + g]);
      }
#pragma unroll
      for (int mt = 0; mt < 2; mt++)
#pragma unroll
        for (int nt = 0; nt < 4; nt++) mma_tf32(acc[mt][nt], a[mt], b[nt]);
    }
    __syncthreads();
  }

  float* p = g_part + (size_t)chunk * (NS * ND);
#pragma unroll
  for (int mt = 0; mt < 2; mt++) {
#pragma unroll
    for (int nt = 0; nt < 4; nt++) {
      const int s = sw + mt * 16 + g;
      const int d = d0 + dw + nt * 8 + t * 2;
      *(float2*)(p + (size_t)s * 512 + d) = make_float2(acc[mt][nt][0], acc[mt][nt][1]);
      *(float2*)(p + (size_t)(s + 8) * 512 + d) = make_float2(acc[mt][nt][2], acc[mt][nt][3]);
    }
  }
}

// ============================================================
// K5b: new_ref = ref + 0.01 * sum(partials)   (deterministic order)
// ============================================================
__global__ __launch_bounds__(256) void k5b_reduce(
    const float* __restrict__ REF, float* __restrict__ OUT_REF) {
  const int idx = blockIdx.x * 256 + threadIdx.x;
  float s = 0.f;
#pragma unroll 8
  for (int c = 0; c < NCHUNK; c++) s += g_part[(size_t)c * (NS * ND) + idx];
  OUT_REF[idx] = REF[idx] + 0.01f * s;
}

// ============================================================
extern "C" void kernel_launch(void* const* d_in, const int* in_sizes, int n_in,
                              void* d_out, int out_size) {
  const float* X   = (const float*)d_in[0];
  const float* REF = (const float*)d_in[1];
  const float* W1  = (const float*)d_in[2];
  const float* b1  = (const float*)d_in[3];
  const float* W2  = (const float*)d_in[4];
  const float* b2  = (const float*)d_in[5];
  const float* WU  = (const float*)d_in[6];
  const float* bu  = (const float*)d_in[7];

  float* out_sel = (float*)d_out;
  float* out_ref = (float*)d_out + (size_t)NB * ND;

  float *w1T, *refT, *w2T, *bt, *rw, *h, *w, *upd;
  cudaGetSymbolAddress((void**)&w1T, g_w1T);
  cudaGetSymbolAddress((void**)&refT, g_refT);
  cudaGetSymbolAddress((void**)&w2T, g_w2T);
  cudaGetSymbolAddress((void**)&bt, g_bt);
  cudaGetSymbolAddress((void**)&rw, g_rw);
  cudaGetSymbolAddress((void**)&h, g_h);
  cudaGetSymbolAddress((void**)&w, g_w);
  cudaGetSymbolAddress((void**)&upd, g_upd);

  dim3 tb(32, 8);
  // weight preprocessing (all tiny)
  k_transpose<<<dim3(4, 16), tb>>>(W1, w1T, 512, 128, 512);    // W1^T tf32
  k_transpose<<<dim3(16, 2), tb>>>(REF, refT, 64, 512, 64);    // ref^T tf32
  k_transpose<<<dim3(2, 4), tb>>>(W2, w2T, 128, 64, 128);      // W2^T tf32
  k_transpose<<<dim3(16, 16), tb>>>(WU, bt, 512, 512, 576);    // Wu1^T -> bt[:, 0:512]
  k_rw<<<8, 256>>>(REF, WU, rw);                               // RW = ref @ Wu2 (f32)
  k_transpose<<<dim3(16, 2), tb>>>(rw, bt + 512, 64, 512, 576);// RW^T -> bt[:, 512:576]

  // K1: h = relu(X @ W1 + b1)   (tf32-rounded store)
  gemm_mma<1, 512, false, true><<<dim3(1, NB / 128), 256>>>(
      X, nullptr, 512, 0, w1T, b1, h, 128);
  // K2: w = softmax(h @ W2 + b2)   (tensor core + register softmax)
  k2_mma<<<NB / 128, 256>>>(w2T, b2);
  // K3: selected = w @ ref   (full-f32 output)
  gemm_mma<0, 64, false, false><<<dim3(4, NB / 128), 256>>>(
      w, nullptr, 64, 0, refT, nullptr, out_sel, 512);
  // K4': updates = tanh([X | w] @ [Wu1; RW] + bu)   K=576
  gemm_mma<2, 576, true, true><<<dim3(4, NB / 128), 256>>>(
      X, w, 512, 64, bt, bu, upd, 512);
  // K5: ref update (deterministic split-K, tensor core)
  k5a_partials<<<NCHUNK * 4, 256>>>();
  k5b_reduce<<<(NS * ND) / 256, 256>>>(REF, out_ref);
}

// round 9
// speedup vs baseline: 4.8544x; 1.0492x over previous
#include <cuda_runtime.h>
#include <math.h>
#include <stdint.h>

#define NB 131072
#define ND 512
#define NS 64
#define NH 128
#define NCHUNK 128
#define CHUNK_ROWS (NB / NCHUNK)   /* 1024 */

// ---- scratch (static device globals; no runtime allocation) ----
static __device__ float g_h[(size_t)NB * NH];             // relu hidden (tf32-rounded)
static __device__ float g_w[(size_t)NB * NS];             // softmax weights (tf32-rounded)
static __device__ float g_upd[(size_t)NB * ND];           // tanh updates (tf32-rounded)
static __device__ float g_part[(size_t)NCHUNK * NS * ND]; // split-K partials
static __device__ float g_w1T[(size_t)NH * ND];           // [128][512] tf32
static __device__ float g_refT[(size_t)ND * NS];          // [512][64] tf32
static __device__ float g_w2T[(size_t)NS * NH];           // [64][128] tf32
static __device__ float g_bt[(size_t)ND * 576];           // [512 n][576 k] = [Wu1^T | RW^T] tf32
static __device__ float g_rw[(size_t)NS * ND];            // RW = ref @ Wu2  [64][512] f32

// ============================================================
// helpers
// ============================================================
__device__ __forceinline__ float f2tf32f(float x) {
  uint32_t r;
  asm("cvt.rna.tf32.f32 %0, %1;" : "=r"(r) : "f"(x));
  return __uint_as_float(r);
}
__device__ __forceinline__ void mma_tf32(float c[4], const uint32_t a[4],
                                         const uint32_t b[2]) {
  asm volatile(
      "mma.sync.aligned.m16n8k8.row.col.f32.tf32.tf32.f32 "
      "{%0,%1,%2,%3}, {%4,%5,%6,%7}, {%8,%9}, {%0,%1,%2,%3};"
      : "+f"(c[0]), "+f"(c[1]), "+f"(c[2]), "+f"(c[3])
      : "r"(a[0]), "r"(a[1]), "r"(a[2]), "r"(a[3]), "r"(b[0]), "r"(b[1]));
}
// ldmatrix x4 on f32 data viewed as b16 pairs: for a 16(row)x8(f32 col) tile,
// returns per-thread {A[g][t], A[g+8][t], A[g][t+4], A[g+8][t+4]} (g=lane>>2, t=lane&3)
__device__ __forceinline__ void ldsm4(uint32_t r[4], uint32_t addr) {
  asm volatile("ldmatrix.sync.aligned.m8n8.x4.shared.b16 {%0,%1,%2,%3}, [%4];"
               : "=r"(r[0]), "=r"(r[1]), "=r"(r[2]), "=r"(r[3]) : "r"(addr));
}
template <int ACT> __device__ __forceinline__ float actf(float x) {
  if (ACT == 1) return x > 0.f ? x : 0.f;
  if (ACT == 2) return tanhf(x);
  return x;
}
#define CP_A16(dst, src)                                              \
  asm volatile("cp.async.cg.shared.global [%0], [%1], 16;"            \
               :: "r"(dst), "l"(__cvta_generic_to_global(src)) : "memory")
#define CP_COMMIT() asm volatile("cp.async.commit_group;" ::: "memory")
#define CP_WAIT0() asm volatile("cp.async.wait_group 0;" ::: "memory")
#define CP_WAIT1() asm volatile("cp.async.wait_group 1;" ::: "memory")

__device__ __forceinline__ uint32_t smem_u32(const void* p) {
  uint32_t a;
  asm("{ .reg .u64 t; cvta.to.shared.u64 t, %1; cvt.u32.u64 %0, t; }"
      : "=r"(a) : "l"(p));
  return a;
}

// ============================================================
// 32x32 transpose + tf32 round: dst[c*dst_stride + r] = tf32(src[r][c])
// grid: (C/32, R/32)
// ============================================================
__global__ void k_transpose(const float* __restrict__ src, float* __restrict__ dst,
                            int R, int C, int dst_stride) {
  __shared__ float t[32][33];
  int c0 = blockIdx.x * 32, r0 = blockIdx.y * 32;
  int x = threadIdx.x, y = threadIdx.y;
#pragma unroll
  for (int i = 0; i < 32; i += 8)
    t[y + i][x] = src[(size_t)(r0 + y + i) * C + c0 + x];
  __syncthreads();
#pragma unroll
  for (int i = 0; i < 32; i += 8)
    dst[(size_t)(c0 + y + i) * dst_stride + r0 + x] = f2tf32f(t[x][y + i]);
}

// ============================================================
// RW = ref @ Wu2  (f32 FFMA; tiny: 64x512x512)
// ============================================================
__global__ __launch_bounds__(256) void k_rw(
    const float* __restrict__ REF, const float* __restrict__ WU,
    float* __restrict__ RW) {
  __shared__ float rs[64][17];
  __shared__ float us[16][68];
  const int tid = threadIdx.x;
  const int n0 = blockIdx.x * 64;
  const int si = (tid >> 4) * 4, ni = (tid & 15) * 4;
  float acc[4][4];
#pragma unroll
  for (int i = 0; i < 4; i++)
#pragma unroll
    for (int j = 0; j < 4; j++) acc[i][j] = 0.f;

  for (int k0 = 0; k0 < 512; k0 += 16) {
    {
      int s = tid >> 2, c4 = (tid & 3) * 4;
      float4 v = *(const float4*)(REF + (size_t)s * 512 + k0 + c4);
      rs[s][c4] = v.x; rs[s][c4 + 1] = v.y; rs[s][c4 + 2] = v.z; rs[s][c4 + 3] = v.w;
    }
    {
      int r = tid >> 4, c4 = (tid & 15) * 4;
      float4 v = *(const float4*)(WU + (size_t)(512 + k0 + r) * 512 + n0 + c4);
      us[r][c4] = v.x; us[r][c4 + 1] = v.y; us[r][c4 + 2] = v.z; us[r][c4 + 3] = v.w;
    }
    __syncthreads();
#pragma unroll
    for (int kk = 0; kk < 16; kk++) {
#pragma unroll
      for (int i = 0; i < 4; i++) {
        float r = rs[si + i][kk];
#pragma unroll
        for (int j = 0; j < 4; j++) acc[i][j] = fmaf(r, us[kk][ni + j], acc[i][j]);
      }
    }
    __syncthreads();
  }
#pragma unroll
  for (int i = 0; i < 4; i++)
#pragma unroll
    for (int j = 0; j < 4; j++)
      RW[(size_t)(si + i) * 512 + n0 + ni + j] = acc[i][j];
}

// ============================================================
// tf32 mma.sync GEMM, cp.async 2-stage pipeline + ldmatrix fragments:
//   OUT[m, n] = ACT( sum_k A[m,k]*BT[n,k] + bias[n] )
// CTA tile 128x128, BK=16; 8 warps 4(m) x 2(n); warp tile 32x64.
// ============================================================
template <int ACT, int KTOT, bool ASPLIT, bool CVT_A>
__global__ __launch_bounds__(256, 2) void gemm_mma(
    const float* __restrict__ A0, const float* __restrict__ A1,
    int a_stride, int a1_stride,
    const float* __restrict__ BT, const float* __restrict__ bias,
    float* __restrict__ OUT, int o_stride) {
  __shared__ float As[2][128][20];
  __shared__ float Bs[2][128][20];
  const int tid = threadIdx.x, wid = tid >> 5, lane = tid & 31;
  const int n0 = blockIdx.x * 128;
  const int m0 = blockIdx.y * 128;
  const int wm = (wid & 3) * 32;
  const int wn = (wid >> 2) * 64;
  const int g = lane >> 2, t = lane & 3;
  // ldmatrix per-thread address decomposition
  const int lrow = ((lane >> 3) & 1) * 8 + (lane & 7);  // row within 16-row block
  const int lcol = (lane >> 4) * 4;                     // 0 or 4

  const uint32_t sA = smem_u32(&As[0][0][0]);
  const uint32_t sB = smem_u32(&Bs[0][0][0]);
  const int row_l = tid >> 2;
  const int c4_l = (tid & 3) * 4;

  float acc[2][8][4];
#pragma unroll
  for (int mt = 0; mt < 2; mt++)
#pragma unroll
    for (int nt = 0; nt < 8; nt++)
#pragma unroll
      for (int r = 0; r < 4; r++) acc[mt][nt][r] = 0.f;

  auto load_tiles = [&](int c, int buf) {
    const int k0 = c * 16;
    const float* Asrc = (!ASPLIT || k0 < 512) ? A0 : A1;
    const int ko = (!ASPLIT || k0 < 512) ? k0 : k0 - 512;
    const int ast = (!ASPLIT || k0 < 512) ? a_stride : a1_stride;
    const uint32_t da = sA + (uint32_t)buf * (128 * 20 * 4);
    const uint32_t db = sB + (uint32_t)buf * (128 * 20 * 4);
#pragma unroll
    for (int l = 0; l < 2; l++) {
      const int row = row_l + l * 64;
      CP_A16(da + (uint32_t)(row * 20 + c4_l) * 4,
             Asrc + (size_t)(m0 + row) * ast + ko + c4_l);
      CP_A16(db + (uint32_t)(row * 20 + c4_l) * 4,
             BT + (size_t)(n0 + row) * KTOT + k0 + c4_l);
    }
  };

  constexpr int NCH = KTOT / 16;
  load_tiles(0, 0);
  CP_COMMIT();
#pragma unroll 1
  for (int c = 0; c < NCH; c++) {
    const int buf = c & 1;
    if (c + 1 < NCH) {
      load_tiles(c + 1, buf ^ 1);
      CP_COMMIT();
      CP_WAIT1();
    } else {
      CP_WAIT0();
    }
    __syncthreads();
    const uint32_t ab = sA + (uint32_t)buf * (128 * 20 * 4);
    const uint32_t bb = sB + (uint32_t)buf * (128 * 20 * 4);
#pragma unroll
    for (int ks = 0; ks < 2; ks++) {
      const int kk = ks * 8;
      uint32_t a[2][4], b[8][2];
#pragma unroll
      for (int mt = 0; mt < 2; mt++) {
        ldsm4(a[mt], ab + (uint32_t)((wm + mt * 16 + lrow) * 20 + kk + lcol) * 4);
        if (CVT_A) {
#pragma unroll
          for (int r = 0; r < 4; r++)
            a[mt][r] = __float_as_uint(f2tf32f(__uint_as_float(a[mt][r])));
        }
      }
#pragma unroll
      for (int p = 0; p < 4; p++) {
        uint32_t t4[4];
        ldsm4(t4, bb + (uint32_t)((wn + p * 16 + lrow) * 20 + kk + lcol) * 4);
        b[2 * p][0] = t4[0]; b[2 * p + 1][0] = t4[1];
        b[2 * p][1] = t4[2]; b[2 * p + 1][1] = t4[3];
      }
#pragma unroll
      for (int mt = 0; mt < 2; mt++)
#pragma unroll
        for (int nt = 0; nt < 8; nt++) mma_tf32(acc[mt][nt], a[mt], b[nt]);
    }
    __syncthreads();
  }

#pragma unroll
  for (int mt = 0; mt < 2; mt++) {
#pragma unroll
    for (int nt = 0; nt < 8; nt++) {
      const int row = m0 + wm + mt * 16 + g;
      const int col = n0 + wn + nt * 8 + t * 2;
      float b0 = 0.f, b1 = 0.f;
      if (bias) { b0 = bias[col]; b1 = bias[col + 1]; }
      float r0 = actf<ACT>(acc[mt][nt][0] + b0);
      float r1 = actf<ACT>(acc[mt][nt][1] + b1);
      float r2 = actf<ACT>(acc[mt][nt][2] + b0);
      float r3 = actf<ACT>(acc[mt][nt][3] + b1);
      if (ACT != 0) { r0 = f2tf32f(r0); r1 = f2tf32f(r1); r2 = f2tf32f(r2); r3 = f2tf32f(r3); }
      *(float2*)(OUT + (size_t)row * o_stride + col) = make_float2(r0, r1);
      *(float2*)(OUT + (size_t)(row + 8) * o_stride + col) = make_float2(r2, r3);
    }
  }
}

// ============================================================
// K2: w = softmax(h @ W2 + b2) via tf32 mma + ldmatrix, softmax in regs.
// CTA: 128 rows; 8 warps, warp = 16 rows x 64 cols; K=128, BK=16.
// ============================================================
__global__ __launch_bounds__(256, 2) void k2_mma(
    const float* __restrict__ W2T, const float* __restrict__ b2) {
  __shared__ float As[2][128][20];
  __shared__ float Bs[2][64][20];
  const int tid = threadIdx.x, wid = tid >> 5, lane = tid & 31;
  const int m0 = blockIdx.x * 128;
  const int g = lane >> 2, t = lane & 3;
  const int lrow = ((lane >> 3) & 1) * 8 + (lane & 7);
  const int lcol = (lane >> 4) * 4;
  const uint32_t sA = smem_u32(&As[0][0][0]);
  const uint32_t sB = smem_u32(&Bs[0][0][0]);

  float acc[8][4];
#pragma unroll
  for (int nt = 0; nt < 8; nt++)
#pragma unroll
    for (int r = 0; r < 4; r++) acc[nt][r] = 0.f;

  auto load = [&](int c, int buf) {
    const int k0 = c * 16;
    const int rowa = tid >> 2, c4 = (tid & 3) * 4;
#pragma unroll
    for (int l = 0; l < 2; l++) {
      const int row = rowa + l * 64;
      CP_A16(sA + (uint32_t)buf * (128 * 20 * 4) + (uint32_t)(row * 20 + c4) * 4,
             g_h + (size_t)(m0 + row) * 128 + k0 + c4);
    }
    if (rowa < 64)
      CP_A16(sB + (uint32_t)buf * (64 * 20 * 4) + (uint32_t)(rowa * 20 + c4) * 4,
             W2T + (size_t)rowa * 128 + k0 + c4);
  };

  load(0, 0);
  CP_COMMIT();
#pragma unroll 1
  for (int c = 0; c < 8; c++) {
    const int buf = c & 1;
    if (c + 1 < 8) { load(c + 1, buf ^ 1); CP_COMMIT(); CP_WAIT1(); }
    else CP_WAIT0();
    __syncthreads();
    const uint32_t ab = sA + (uint32_t)buf * (128 * 20 * 4);
    const uint32_t bb = sB + (uint32_t)buf * (64 * 20 * 4);
#pragma unroll
    for (int ks = 0; ks < 2; ks++) {
      const int kk = ks * 8;
      uint32_t a[4], b[8][2];
      ldsm4(a, ab + (uint32_t)((wid * 16 + lrow) * 20 + kk + lcol) * 4);
#pragma unroll
      for (int p = 0; p < 4; p++) {
        uint32_t t4[4];
        ldsm4(t4, bb + (uint32_t)((p * 16 + lrow) * 20 + kk + lcol) * 4);
        b[2 * p][0] = t4[0]; b[2 * p + 1][0] = t4[1];
        b[2 * p][1] = t4[2]; b[2 * p + 1][1] = t4[3];
      }
#pragma unroll
      for (int nt = 0; nt < 8; nt++) mma_tf32(acc[nt], a, b[nt]);
    }
    __syncthreads();
  }

#pragma unroll
  for (int nt = 0; nt < 8; nt++) {
    float2 bb = *(const float2*)(b2 + nt * 8 + t * 2);
    acc[nt][0] += bb.x; acc[nt][1] += bb.y;
    acc[nt][2] += bb.x; acc[nt][3] += bb.y;
  }
  float m0v = -1e30f, m1v = -1e30f;
#pragma unroll
  for (int nt = 0; nt < 8; nt++) {
    m0v = fmaxf(m0v, fmaxf(acc[nt][0], acc[nt][1]));
    m1v = fmaxf(m1v, fmaxf(acc[nt][2], acc[nt][3]));
  }
#pragma unroll
  for (int o = 1; o <= 2; o <<= 1) {
    m0v = fmaxf(m0v, __shfl_xor_sync(~0u, m0v, o));
    m1v = fmaxf(m1v, __shfl_xor_sync(~0u, m1v, o));
  }
  float s0 = 0.f, s1 = 0.f;
#pragma unroll
  for (int nt = 0; nt < 8; nt++) {
    acc[nt][0] = __expf(acc[nt][0] - m0v); s0 += acc[nt][0];
    acc[nt][1] = __expf(acc[nt][1] - m0v); s0 += acc[nt][1];
    acc[nt][2] = __expf(acc[nt][2] - m1v); s1 += acc[nt][2];
    acc[nt][3] = __expf(acc[nt][3] - m1v); s1 += acc[nt][3];
  }
#pragma unroll
  for (int o = 1; o <= 2; o <<= 1) {
    s0 += __shfl_xor_sync(~0u, s0, o);
    s1 += __shfl_xor_sync(~0u, s1, o);
  }
  const float i0 = 1.f / s0, i1 = 1.f / s1;
  const int r0 = m0 + wid * 16 + g;
#pragma unroll
  for (int nt = 0; nt < 8; nt++) {
    const int col = nt * 8 + t * 2;
    *(float2*)(g_w + (size_t)r0 * 64 + col) =
        make_float2(f2tf32f(acc[nt][0] * i0), f2tf32f(acc[nt][1] * i0));
    *(float2*)(g_w + (size_t)(r0 + 8) * 64 + col) =
        make_float2(f2tf32f(acc[nt][2] * i1), f2tf32f(acc[nt][3] * i1));
  }
}

// ============================================================
// K5a: split-K partials of w^T @ updates via tf32 mma.
// C tile [64 s x 128 d]; warps 2(s) x 4(d). (scalar LDS fragments:
// operands are k-major in smem; ldmatrix.trans is b16-granular, N/A)
// ============================================================
__global__ __launch_bounds__(256) void k5a_partials() {
  const int dq    = blockIdx.x & 3;
  const int chunk = blockIdx.x >> 2;
  const int d0 = dq * 128;
  const int b0 = chunk * CHUNK_ROWS;
  __shared__ float wt[2][16][68];
  __shared__ float ut[2][16][132];
  const int tid = threadIdx.x, wid = tid >> 5, lane = tid & 31;
  const int sw = (wid & 1) * 32, dw = (wid >> 1) * 32;
  const int g = lane >> 2, t = lane & 3;
  const uint32_t sW = smem_u32(&wt[0][0][0]);
  const uint32_t sU = smem_u32(&ut[0][0][0]);

  float acc[2][4][4];
#pragma unroll
  for (int mt = 0; mt < 2; mt++)
#pragma unroll
    for (int nt = 0; nt < 4; nt++)
#pragma unroll
      for (int r = 0; r < 4; r++) acc[mt][nt][r] = 0.f;

  auto load = [&](int c, int buf) {
    const int k0 = c * 16;
    {
      const int row = tid >> 4, c4 = (tid & 15) * 4;
      CP_A16(sW + (uint32_t)buf * (16 * 68 * 4) + (uint32_t)(row * 68 + c4) * 4,
             g_w + (size_t)(b0 + k0 + row) * 64 + c4);
    }
#pragma unroll
    for (int l = 0; l < 2; l++) {
      const int lin = tid + l * 256;
      const int row = lin >> 5, c4 = (lin & 31) * 4;
      CP_A16(sU + (uint32_t)buf * (16 * 132 * 4) + (uint32_t)(row * 132 + c4) * 4,
             g_upd + (size_t)(b0 + k0 + row) * 512 + d0 + c4);
    }
  };

  constexpr int NCH = CHUNK_ROWS / 16;
  load(0, 0);
  CP_COMMIT();
#pragma unroll 1
  for (int c = 0; c < NCH; c++) {
    const int buf = c & 1;
    if (c + 1 < NCH) { load(c + 1, buf ^ 1); CP_COMMIT(); CP_WAIT1(); }
    else CP_WAIT0();
    __syncthreads();
#pragma unroll
    for (int ks = 0; ks < 2; ks++) {
      const int kk = ks * 8;
      uint32_t a[2][4], b[4][2];
#pragma unroll
      for (int mt = 0; mt < 2; mt++) {
        const int sb = sw + mt * 16;
        a[mt][0] = __float_as_uint(wt[buf][kk + t][sb + g]);
        a[mt][1] = __float_as_uint(wt[buf][kk + t][sb + 8 + g]);
        a[mt][2] = __float_as_uint(wt[buf][kk + t + 4][sb + g]);
        a[mt][3] = __float_as_uint(wt[buf][kk + t + 4][sb + 8 + g]);
      }
#pragma unroll
      for (int nt = 0; nt < 4; nt++) {
        const int db = dw + nt * 8;
        b[nt][0] = __float_as_uint(ut[buf][kk + t][db + g]);
        b[nt][1] = __float_as_uint(ut[buf][kk + t + 4][db + g]);
      }
#pragma unroll
      for (int mt = 0; mt < 2; mt++)
#pragma unroll
        for (int nt = 0; nt < 4; nt++) mma_tf32(acc[mt][nt], a[mt], b[nt]);
    }
    __syncthreads();
  }

  float* p = g_part + (size_t)chunk * (NS * ND);
#pragma unroll
  for (int mt = 0; mt < 2; mt++) {
#pragma unroll
    for (int nt = 0; nt < 4; nt++) {
      const int s = sw + mt * 16 + g;
      const int d = d0 + dw + nt * 8 + t * 2;
      *(float2*)(p + (size_t)s * 512 + d) = make_float2(acc[mt][nt][0], acc[mt][nt][1]);
      *(float2*)(p + (size_t)(s + 8) * 512 + d) = make_float2(acc[mt][nt][2], acc[mt][nt][3]);
    }
  }
}

// ============================================================
// K5b: new_ref = ref + 0.01 * sum(partials)   (deterministic order)
// ============================================================
__global__ __launch_bounds__(256) void k5b_reduce(
    const float* __restrict__ REF, float* __restrict__ OUT_REF) {
  const int idx = blockIdx.x * 256 + threadIdx.x;
  float s = 0.f;
#pragma unroll 8
  for (int c = 0; c < NCHUNK; c++) s += g_part[(size_t)c * (NS * ND) + idx];
  OUT_REF[idx] = REF[idx] + 0.01f * s;
}

// ============================================================
extern "C" void kernel_launch(void* const* d_in, const int* in_sizes, int n_in,
                              void* d_out, int out_size) {
  const float* X   = (const float*)d_in[0];
  const float* REF = (const float*)d_in[1];
  const float* W1  = (const float*)d_in[2];
  const float* b1  = (const float*)d_in[3];
  const float* W2  = (const float*)d_in[4];
  const float* b2  = (const float*)d_in[5];
  const float* WU  = (const float*)d_in[6];
  const float* bu  = (const float*)d_in[7];

  float* out_sel = (float*)d_out;
  float* out_ref = (float*)d_out + (size_t)NB * ND;

  float *w1T, *refT, *w2T, *bt, *rw, *h, *w, *upd;
  cudaGetSymbolAddress((void**)&w1T, g_w1T);
  cudaGetSymbolAddress((void**)&refT, g_refT);
  cudaGetSymbolAddress((void**)&w2T, g_w2T);
  cudaGetSymbolAddress((void**)&bt, g_bt);
  cudaGetSymbolAddress((void**)&rw, g_rw);
  cudaGetSymbolAddress((void**)&h, g_h);
  cudaGetSymbolAddress((void**)&w, g_w);
  cudaGetSymbolAddress((void**)&upd, g_upd);

  dim3 tb(32, 8);
  // weight preprocessing (all tiny)
  k_transpose<<<dim3(4, 16), tb>>>(W1, w1T, 512, 128, 512);    // W1^T tf32
  k_transpose<<<dim3(16, 2), tb>>>(REF, refT, 64, 512, 64);    // ref^T tf32
  k_transpose<<<dim3(2, 4), tb>>>(W2, w2T, 128, 64, 128);      // W2^T tf32
  k_transpose<<<dim3(16, 16), tb>>>(WU, bt, 512, 512, 576);    // Wu1^T -> bt[:, 0:512]
  k_rw<<<8, 256>>>(REF, WU, rw);                               // RW = ref @ Wu2 (f32)
  k_transpose<<<dim3(16, 2), tb>>>(rw, bt + 512, 64, 512, 576);// RW^T -> bt[:, 512:576]

  // K1: h = relu(X @ W1 + b1)   (tf32-rounded store)
  gemm_mma<1, 512, false, true><<<dim3(1, NB / 128), 256>>>(
      X, nullptr, 512, 0, w1T, b1, h, 128);
  // K2: w = softmax(h @ W2 + b2)
  k2_mma<<<NB / 128, 256>>>(w2T, b2);
  // K3: selected = w @ ref   (full-f32 output)
  gemm_mma<0, 64, false, false><<<dim3(4, NB / 128), 256>>>(
      w, nullptr, 64, 0, refT, nullptr, out_sel, 512);
  // K4': updates = tanh([X | w] @ [Wu1; RW] + bu)   K=576
  gemm_mma<2, 576, true, true><<<dim3(4, NB / 128), 256>>>(
      X, w, 512, 64, bt, bu, upd, 512);
  // K5: ref update (deterministic split-K, tensor core)
  k5a_partials<<<NCHUNK * 4, 256>>>();
  k5b_reduce<<<(NS * ND) / 256, 256>>>(REF, out_ref);
}